// round 8
// baseline (speedup 1.0000x reference)
#include <cuda_runtime.h>
#include <cuda_fp16.h>
#include <cstdint>

#define NLAYERS 25
#define KOUT 50
#define FW 1266
#define ROWS 64
#define THREADS 1024
#define TOTALC 253
#define CK 4
#define NBUF 3
#define RSE 1272                         // fp16 elems per A row (2544B, 16B-aligned, LDSM conflict-free)
#define A_BYTES (ROWS * RSE * 2)         // 162816
#define KSB 3584                         // per-ks W block: 7 nt * 32 lanes * 16B
#define CHUNK_B (CK * KSB)               // 14336
#define WOFF A_BYTES                     // 162816
#define SCOFF (WOFF + NBUF * CHUNK_B)    // 205824
#define SMEM_TOTAL (SCOFF + 16384)       // 222208

// packed-linear W fragments: [gchunk(253)][ksl(4)][nt(7)][lane(32)][word(4)]
// word = {bhi_r0, bhi_r1, blo_r0, blo_r1} -> one LDS.128 per (ks, tile)
#define WFRAG_U32 (TOTALC * (CHUNK_B / 4))   // 906,752 words = 3.63 MB
__device__ uint32_t g_wfrag[WFRAG_U32];

__constant__ int CSTART[26] = {0,1,3,5,8,12,17,22,28,35,43,52,61,71,82,94,
                               106,119,133,148,164,180,197,215,234,253};

__device__ __forceinline__ uint32_t packh2(__half a, __half b) {
    return (uint32_t)__half_as_ushort(a) | ((uint32_t)__half_as_ushort(b) << 16);
}

// ---- prekernel: fp32 W -> fragment-ordered fp16 hi/lo quads, chunk-linear ----
__global__ void stage_w_kernel(const float* __restrict__ Ws) {
    int i = blockIdx.x * 256 + threadIdx.x;
    if (i >= WFRAG_U32) return;
    int gchunk = i / 3584, off = i % 3584;
    int layer = 0;
    while (layer < NLAYERS - 1 && CSTART[layer + 1] <= gchunk) layer++;
    int c = gchunk - CSTART[layer];
    int ksl = off / 896, o3 = off % 896;
    int nt = o3 / 128,  rem = o3 % 128;
    int ln = rem / 4,   word = rem % 4;
    int plane = word >> 1, reg = word & 1;
    int n = nt * 8 + (ln >> 2);
    int k = (c * CK + ksl) * 16 + ((ln & 3) << 1) + reg * 8;
    float w0 = 0.f, w1 = 0.f;
    if (n < KOUT && k + 1 < FW) {
        const float* p = Ws + ((size_t)layer * KOUT + n) * FW + k;
        w0 = p[0]; w1 = p[1];
    }
    uint32_t v;
    if (plane == 0) {
        v = packh2(__float2half_rn(w0), __float2half_rn(w1));
    } else {
        __half h0 = __float2half_rn(w0), h1 = __float2half_rn(w1);
        v = packh2(__float2half_rn(w0 - __half2float(h0)),
                   __float2half_rn(w1 - __half2float(h1)));
    }
    g_wfrag[i] = v;
}

#define MMA(d, a, b0_, b1_) \
    asm volatile("mma.sync.aligned.m16n8k16.row.col.f32.f16.f16.f32 " \
        "{%0,%1,%2,%3},{%4,%5,%6,%7},{%8,%9},{%0,%1,%2,%3};" \
        : "+f"(d[0]), "+f"(d[1]), "+f"(d[2]), "+f"(d[3]) \
        : "r"(a[0]), "r"(a[1]), "r"(a[2]), "r"(a[3]), "r"(b0_), "r"(b1_))

#define LDSM4(r, addr) \
    asm volatile("ldmatrix.sync.aligned.m8n8.x4.shared.b16 {%0,%1,%2,%3}, [%4];" \
        : "=r"(r[0]), "=r"(r[1]), "=r"(r[2]), "=r"(r[3]) : "r"(addr))

__device__ __forceinline__ void cp16(uint32_t dst, const void* src) {
    asm volatile("cp.async.cg.shared.global [%0], [%1], 16;" :: "r"(dst), "l"(src));
}

__global__ void __launch_bounds__(THREADS, 1) value_model_mma_kernel(
    const float* __restrict__ state,
    const float* __restrict__ bs,
    const float* __restrict__ Wout,
    const float* __restrict__ bout,
    float* __restrict__ out)
{
    extern __shared__ char smraw[];
    __half* A = (__half*)smraw;
    const uint32_t smb = (uint32_t)__cvta_generic_to_shared(smraw);
    float4* scratch4 = (float4*)(smraw + SCOFF);

    const int tid  = threadIdx.x;
    const int lane = tid & 31;
    const int wid  = tid >> 5;
    const int cta  = blockIdx.x;
    const int kg   = wid >> 3;         // 0..3: ks within chunk
    const int sub  = wid & 7;          // (mt_g, ng) id
    const int mt_g = sub & 1;          // row half: rows mt_g*32 .. +31
    const int ng   = sub >> 1;         // n-tile pair: tiles 2ng, 2ng+1 (<7)

    // ---- zero A plane ----
    {
        uint4 z = make_uint4(0u, 0u, 0u, 0u);
        uint4* p = (uint4*)smraw;
        for (int i = tid; i < A_BYTES / 16; i += THREADS) p[i] = z;
    }
    __syncthreads();

    // ---- initial state (64 x 16) ----
    if (tid < ROWS * 16) {
        int r = tid >> 4, j = tid & 15;
        A[r * RSE + j] = __float2half_rn(state[(cta * ROWS + r) * 16 + j]);
    }
    __syncthreads();

    // ldmatrix bases: this warp's two m16 tiles (rows mt_g*32, mt_g*32+16)
    const uint32_t abase = smb + (uint32_t)((mt_g * 32 + (lane & 15)) * RSE) * 2u
                               + (uint32_t)(lane >> 4) * 16u;

    // per-thread staging addresses (1 cp.async per thread per chunk)
    const bool stg = (tid < CHUNK_B / 16);          // 896 stagers
    const char* ssrc = (const char*)g_wfrag + (size_t)tid * 16;
    const uint32_t sdst = smb + WOFF + (uint32_t)tid * 16;

    // ---- prime: stage chunks 0,1 ----
    if (stg) cp16(sdst, ssrc);
    asm volatile("cp.async.commit_group;");
    if (stg) cp16(sdst + CHUNK_B, ssrc + CHUNK_B);
    asm volatile("cp.async.commit_group;");

    int gj = 0;
    int width = 16;
    for (int l = 0; l < NLAYERS; l++) {
        const int nks = (31 + 50 * l) >> 4;
        const int nch = CSTART[l + 1] - CSTART[l];

        float acc[2][2][4] = {};   // [mt_local][nt_local][reg]

        for (int c = 0; c < nch; c++) {
            asm volatile("cp.async.wait_group 1;" ::: "memory");   // chunk gj landed
            __syncthreads();                                       // publish + free (gj-1)'s buffer
            // stage chunk gj+2 into buffer (gj+2)%3 (freed: consumed at gj-1)
            if (gj + 2 < TOTALC && stg) {
                int b = gj + 2; int bm = b % NBUF;
                cp16(smb + WOFF + (uint32_t)bm * CHUNK_B + (uint32_t)tid * 16,
                     (const char*)g_wfrag + (size_t)b * CHUNK_B + (size_t)tid * 16);
            }
            asm volatile("cp.async.commit_group;");                // uniform group count
            // compute: this warp's single ks in chunk gj
            const int ks = c * CK + kg;
            if (ks < nks) {
                uint32_t a0[4], a1[4];
                const uint32_t ad = abase + (uint32_t)ks * 32u;
                LDSM4(a0, ad);
                LDSM4(a1, ad + 16u * RSE * 2u);
                const char* wbuf = smraw + WOFF + (size_t)(gj % NBUF) * CHUNK_B
                                 + (size_t)kg * KSB;
                #pragma unroll
                for (int t = 0; t < 2; t++) {
                    const int tile = ng * 2 + t;
                    if (tile < 7) {
                        const uint4 b = *((const uint4*)wbuf + tile * 32 + lane);
                        MMA(acc[0][t], a0, b.x, b.y);
                        MMA(acc[0][t], a0, b.z, b.w);
                        MMA(acc[1][t], a1, b.x, b.y);
                        MMA(acc[1][t], a1, b.z, b.w);
                    }
                }
            }
            gj++;
        }

        // ---- 3-wave kg-reduction (16KB scratch), then epilogue by kg==0 ----
        #pragma unroll
        for (int q = 1; q <= 3; q++) {
            if (kg == q) {
                #pragma unroll
                for (int mt = 0; mt < 2; mt++)
                    #pragma unroll
                    for (int t = 0; t < 2; t++)
                        scratch4[sub * 128 + (mt * 2 + t) * 32 + lane] =
                            make_float4(acc[mt][t][0], acc[mt][t][1],
                                        acc[mt][t][2], acc[mt][t][3]);
            }
            __syncthreads();
            if (kg == 0) {
                #pragma unroll
                for (int mt = 0; mt < 2; mt++)
                    #pragma unroll
                    for (int t = 0; t < 2; t++) {
                        float4 v = scratch4[sub * 128 + (mt * 2 + t) * 32 + lane];
                        acc[mt][t][0] += v.x; acc[mt][t][1] += v.y;
                        acc[mt][t][2] += v.z; acc[mt][t][3] += v.w;
                    }
            }
            __syncthreads();
        }

        if (kg == 0) {
            #pragma unroll
            for (int mt = 0; mt < 2; mt++)
                #pragma unroll
                for (int t = 0; t < 2; t++) {
                    const int tile = ng * 2 + t;
                    if (tile < 7) {
                        #pragma unroll
                        for (int half = 0; half < 2; half++) {
                            const int n = tile * 8 + ((lane & 3) << 1) + half;
                            if (n < KOUT) {
                                const float bz = __ldg(bs + l * KOUT + n);
                                #pragma unroll
                                for (int rr = 0; rr < 2; rr++) {
                                    float y = acc[mt][t][rr * 2 + half] + bz;
                                    y = (y > 0.f) ? y : 0.01f * y;
                                    const int r = mt_g * 32 + mt * 16
                                                + (lane >> 2) + rr * 8;
                                    A[r * RSE + width + n] = __float2half_rn(y);
                                }
                            }
                        }
                    }
                }
        }
        width += KOUT;
        // next chunk's top barrier orders epilogue stores before LDSM reads
    }

    __syncthreads();

    // ---- final projection: out[r] = x . Wout + bout ----
    #pragma unroll
    for (int t = 0; t < 2; t++) {
        const int r = wid * 2 + t;
        float s = 0.f;
        for (int j = lane; j < FW; j += 32)
            s += __half2float(A[r * RSE + j]) * Wout[j];
        #pragma unroll
        for (int o = 16; o; o >>= 1) s += __shfl_xor_sync(0xffffffffu, s, o);
        if (lane == 0) out[cta * ROWS + r] = s + bout[0];
    }
}

extern "C" void kernel_launch(void* const* d_in, const int* in_sizes, int n_in,
                              void* d_out, int out_size) {
    const float* state = (const float*)d_in[0];
    const float* Ws    = (const float*)d_in[1];
    const float* bs    = (const float*)d_in[2];
    const float* Wout  = (const float*)d_in[3];
    const float* bout  = (const float*)d_in[4];
    float* out = (float*)d_out;

    const int B = in_sizes[0] / 16;   // 32768

    stage_w_kernel<<<(WFRAG_U32 + 255) / 256, 256>>>(Ws);

    cudaFuncSetAttribute(value_model_mma_kernel,
                         cudaFuncAttributeMaxDynamicSharedMemorySize, SMEM_TOTAL);
    value_model_mma_kernel<<<B / ROWS, THREADS, SMEM_TOTAL>>>(state, bs, Wout, bout, out);
}

// round 10
// speedup vs baseline: 1.5584x; 1.5584x over previous
#include <cuda_runtime.h>
#include <cuda_fp16.h>
#include <cstdint>

#define NLAYERS 25
#define KOUT 50
#define FW 1266
#define ROWS 64
#define THREADS 512
#define MAXKS 76
#define NT 7
#define RSE 1272                         // fp16 elems/row (2544B, 16B-aligned)
#define A_BYTES (ROWS * RSE * 2)         // 162816
#define WOFF A_BYTES
#define KSB 1792                         // per-ks W block: 7 nt * 32 lanes * 8B (hi plane only)
#define WBUF (8 * KSB)                   // 14336 (8-ks chunk)
#define SMEM_TOTAL (WOFF + 2 * WBUF)     // 191488

// W fragments: [layer][ks(76)][nt(7)][lane(32)][word(2)]; word = {bhi_r0, bhi_r1}
#define WFRAG_WORDS (NLAYERS * MAXKS * NT * 32 * 2)   // 851,200 (3.4 MB)
__device__ uint32_t g_wfrag[WFRAG_WORDS];

__device__ __forceinline__ uint32_t packh2(__half a, __half b) {
    return (uint32_t)__half_as_ushort(a) | ((uint32_t)__half_as_ushort(b) << 16);
}

// ---- prekernel: fp32 W -> fragment-ordered fp16 pairs (identical mapping to R4, hi only) ----
__global__ void stage_w_kernel(const float* __restrict__ Ws) {
    int i = blockIdx.x * blockDim.x + threadIdx.x;
    if (i >= WFRAG_WORDS) return;
    int w = i;
    int reg  = w & 1;  w >>= 1;
    int ln   = w & 31; w >>= 5;
    int nt   = w % NT; w /= NT;
    int ks   = w % MAXKS;
    int layer = w / MAXKS;
    int n = nt * 8 + (ln >> 2);
    int k = ks * 16 + ((ln & 3) << 1) + reg * 8;   // k <= 1214, always in-bounds
    float w0 = 0.f, w1 = 0.f;
    if (n < KOUT) {
        const float* p = Ws + ((size_t)layer * KOUT + n) * FW + k;
        w0 = p[0]; w1 = p[1];
    }
    g_wfrag[i] = packh2(__float2half_rn(w0), __float2half_rn(w1));
}

#define MMA(d, a, b0_, b1_) \
    asm volatile("mma.sync.aligned.m16n8k16.row.col.f32.f16.f16.f32 " \
        "{%0,%1,%2,%3},{%4,%5,%6,%7},{%8,%9},{%0,%1,%2,%3};" \
        : "+f"(d[0]), "+f"(d[1]), "+f"(d[2]), "+f"(d[3]) \
        : "r"(a[0]), "r"(a[1]), "r"(a[2]), "r"(a[3]), "r"(b0_), "r"(b1_))

#define LDSM4(r, addr) \
    asm volatile("ldmatrix.sync.aligned.m8n8.x4.shared.b16 {%0,%1,%2,%3}, [%4];" \
        : "=r"(r[0]), "=r"(r[1]), "=r"(r[2]), "=r"(r[3]) : "r"(addr))

__device__ __forceinline__ void cp16(uint32_t dst, const void* src) {
    asm volatile("cp.async.cg.shared.global [%0], [%1], 16;" :: "r"(dst), "l"(src));
}

__global__ void __launch_bounds__(THREADS, 1) value_model_mma_kernel(
    const float* __restrict__ state,
    const float* __restrict__ bs,
    const float* __restrict__ Wout,
    const float* __restrict__ bout,
    float* __restrict__ out)
{
    extern __shared__ char smraw[];
    __half* A = (__half*)smraw;
    const uint32_t sm_u32 = (uint32_t)__cvta_generic_to_shared(smraw);

    const int tid  = threadIdx.x;
    const int lane = tid & 31;
    const int wid  = tid >> 5;
    const int cta  = blockIdx.x;
    const int kg   = wid >> 2;         // 0..3: k-split within 8-ks chunk (2 ks each)
    const int m    = (wid >> 1) & 1;   // row-half: rows m*32 .. m*32+31
    const int ng   = wid & 1;          // n-group: tiles ng*4 .. (<7)
    const int sub  = wid & 3;          // (m, ng) id

    // ---- zero A plane ----
    {
        uint4 z = make_uint4(0u, 0u, 0u, 0u);
        uint4* p = (uint4*)smraw;
        for (int i = tid; i < A_BYTES / 16; i += THREADS) p[i] = z;
    }
    __syncthreads();

    // ---- initial state (64 x 16) ----
    for (int idx = tid; idx < ROWS * 16; idx += THREADS) {
        int r = idx >> 4, j = idx & 15;
        A[r * RSE + j] = __float2half_rn(state[(cta * ROWS + r) * 16 + j]);
    }
    __syncthreads();

    // ldmatrix base for this warp's two m16 tiles (rows m*32 and m*32+16)
    const uint32_t abase = sm_u32 + (uint32_t)((m * 32 + (lane & 15)) * RSE) * 2u
                                  + (uint32_t)(lane >> 4) * 16u;
    const uint32_t wsm = sm_u32 + WOFF;
    float4* scratch4 = (float4*)(smraw + WOFF);   // overlays W buffers (dead at epilogue)

    int width = 16;
    for (int l = 0; l < NLAYERS; l++) {
        const int nks = (width + 15) >> 4;
        const int nc  = (nks + 7) >> 3;

        float acc[2][4][4] = {};

        // prologue: stage chunk 0
        {
            const int ksn0 = (nks < 8) ? nks : 8;
            const char* src = (const char*)g_wfrag + (size_t)(l * MAXKS) * KSB;
            const int nops = ksn0 * 112;
            for (int i = tid; i < nops; i += THREADS) cp16(wsm + i * 16, src + (size_t)i * 16);
            asm volatile("cp.async.commit_group;");
        }

        for (int c = 0; c < nc; c++) {
            if (c + 1 < nc) {
                const int rem = nks - (c + 1) * 8;
                const int ksn1 = (rem < 8) ? rem : 8;
                const char* src = (const char*)g_wfrag
                                + (size_t)(l * MAXKS + (c + 1) * 8) * KSB;
                uint32_t dst = wsm + (((c + 1) & 1) ? WBUF : 0);
                const int nops = ksn1 * 112;
                for (int i = tid; i < nops; i += THREADS) cp16(dst + i * 16, src + (size_t)i * 16);
                asm volatile("cp.async.commit_group;");
                asm volatile("cp.async.wait_group 1;");
            } else {
                asm volatile("cp.async.wait_group 0;");
            }
            __syncthreads();

            const uint32_t* wb = (const uint32_t*)(smraw + WOFF + ((c & 1) ? WBUF : 0));
            const int ksn = min(8, nks - c * 8);

            #pragma unroll
            for (int i = 0; i < 2; i++) {
                const int ksl = kg * 2 + i;
                if (ksl < ksn) {
                    const int ks = c * 8 + ksl;
                    uint32_t a0[4], a1[4];
                    const uint32_t ad = abase + (uint32_t)ks * 32u;
                    LDSM4(a0, ad);
                    LDSM4(a1, ad + 16u * RSE * 2u);
                    const uint32_t* wk = wb + ksl * 448;
                    #pragma unroll
                    for (int t = 0; t < 4; t++) {
                        const int tile = ng * 4 + t;
                        if (tile < NT) {
                            const uint2 b = *(const uint2*)(wk + tile * 64 + lane * 2);
                            MMA(acc[0][t], a0, b.x, b.y);
                            MMA(acc[1][t], a1, b.x, b.y);
                        }
                    }
                }
            }
            __syncthreads();
        }

        // ---- epilogue: 3-wave kg-reduction (16KB scratch, R8-proven), bias + leaky, append ----
        #pragma unroll
        for (int q = 1; q <= 3; q++) {
            if (kg == q) {
                #pragma unroll
                for (int mt = 0; mt < 2; mt++)
                    #pragma unroll
                    for (int t = 0; t < 4; t++)
                        scratch4[sub * 256 + (mt * 4 + t) * 32 + lane] =
                            make_float4(acc[mt][t][0], acc[mt][t][1],
                                        acc[mt][t][2], acc[mt][t][3]);
            }
            __syncthreads();
            if (kg == 0) {
                #pragma unroll
                for (int mt = 0; mt < 2; mt++)
                    #pragma unroll
                    for (int t = 0; t < 4; t++) {
                        float4 v = scratch4[sub * 256 + (mt * 4 + t) * 32 + lane];
                        acc[mt][t][0] += v.x; acc[mt][t][1] += v.y;
                        acc[mt][t][2] += v.z; acc[mt][t][3] += v.w;
                    }
            }
            __syncthreads();
        }

        if (kg == 0) {
            #pragma unroll
            for (int mt = 0; mt < 2; mt++)
                #pragma unroll
                for (int t = 0; t < 4; t++) {
                    const int tile = ng * 4 + t;
                    if (tile < NT) {
                        const int n0 = tile * 8 + ((lane & 3) << 1);
                        const int rbase = m * 32 + mt * 16 + (lane >> 2);
                        #pragma unroll
                        for (int half = 0; half < 2; half++) {
                            const int n = n0 + half;
                            if (n < KOUT) {
                                const float bz = bs[l * KOUT + n];
                                #pragma unroll
                                for (int rr = 0; rr < 2; rr++) {
                                    float y = acc[mt][t][rr * 2 + half] + bz;
                                    y = (y > 0.f) ? y : 0.01f * y;
                                    A[(rbase + rr * 8) * RSE + width + n] =
                                        __float2half_rn(y);
                                }
                            }
                        }
                    }
                }
        }
        width += KOUT;
        __syncthreads();
    }

    // ---- final projection: out[r] = x . Wout + bout ----
    #pragma unroll
    for (int t = 0; t < 4; t++) {
        const int r = wid * 4 + t;
        float s = 0.f;
        for (int j = lane; j < FW; j += 32)
            s += __half2float(A[r * RSE + j]) * Wout[j];
        #pragma unroll
        for (int o = 16; o; o >>= 1) s += __shfl_xor_sync(0xffffffffu, s, o);
        if (lane == 0) out[cta * ROWS + r] = s + bout[0];
    }
}

extern "C" void kernel_launch(void* const* d_in, const int* in_sizes, int n_in,
                              void* d_out, int out_size) {
    const float* state = (const float*)d_in[0];
    const float* Ws    = (const float*)d_in[1];
    const float* bs    = (const float*)d_in[2];
    const float* Wout  = (const float*)d_in[3];
    const float* bout  = (const float*)d_in[4];
    float* out = (float*)d_out;

    const int B = in_sizes[0] / 16;   // 32768

    stage_w_kernel<<<(WFRAG_WORDS + 255) / 256, 256>>>(Ws);

    cudaFuncSetAttribute(value_model_mma_kernel,
                         cudaFuncAttributeMaxDynamicSharedMemorySize, SMEM_TOTAL);
    value_model_mma_kernel<<<B / ROWS, THREADS, SMEM_TOTAL>>>(state, bs, Wout, bout, out);
}